// round 7
// baseline (speedup 1.0000x reference)
#include <cuda_runtime.h>
#include <cuda_bf16.h>

// BlockDiagAttention: B=4,H=16,N=4128,D=64. fp32 in/out.
// R7: split-bf16 mma + ldmatrix. Single front load phase (Q,K,V all converted
// to dedicated split buffers) -> ONE barrier total, no mid-kernel V bubble.
// 4 CTAs/SM, 55.3KB smem. Eager P-split, deferred softmax normalization.
#define NSEQ  4128
#define TILES 65
#define QSTR  36   // u32 per smem row (144 B)

__device__ __forceinline__ void mma16816(float c[4], const unsigned a[4],
                                         const unsigned b[2]) {
    asm volatile(
        "mma.sync.aligned.m16n8k16.row.col.f32.bf16.bf16.f32 "
        "{%0,%1,%2,%3}, {%4,%5,%6,%7}, {%8,%9}, {%0,%1,%2,%3};"
        : "+f"(c[0]), "+f"(c[1]), "+f"(c[2]), "+f"(c[3])
        : "r"(a[0]), "r"(a[1]), "r"(a[2]), "r"(a[3]), "r"(b[0]), "r"(b[1]));
}

__device__ __forceinline__ void ldsm_x4(unsigned r[4], unsigned addr) {
    asm volatile("ldmatrix.sync.aligned.m8n8.x4.shared.b16 {%0,%1,%2,%3}, [%4];"
                 : "=r"(r[0]), "=r"(r[1]), "=r"(r[2]), "=r"(r[3]) : "r"(addr));
}

__device__ __forceinline__ void ldsm_x4_t(unsigned r[4], unsigned addr) {
    asm volatile("ldmatrix.sync.aligned.m8n8.x4.trans.shared.b16 {%0,%1,%2,%3}, [%4];"
                 : "=r"(r[0]), "=r"(r[1]), "=r"(r[2]), "=r"(r[3]) : "r"(addr));
}

__device__ __forceinline__ void split2(float x0, float x1, unsigned& h, unsigned& l) {
    __nv_bfloat162 hh = __floats2bfloat162_rn(x0, x1);
    float r0 = x0 - __bfloat162float(hh.x);
    float r1 = x1 - __bfloat162float(hh.y);
    __nv_bfloat162 ll = __floats2bfloat162_rn(r0, r1);
    h = *(unsigned*)&hh;
    l = *(unsigned*)&ll;
}

extern __shared__ unsigned smem_u32[];

__global__ __launch_bounds__(128, 4)
void bd_attn_kernel(const float* __restrict__ q, const float* __restrict__ k,
                    const float* __restrict__ v, float* __restrict__ out)
{
    unsigned* sQh = smem_u32;
    unsigned* sQl = smem_u32 + 64 * QSTR;
    unsigned* sKh = smem_u32 + 2 * 64 * QSTR;
    unsigned* sKl = smem_u32 + 3 * 64 * QSTR;
    unsigned* sVh = smem_u32 + 4 * 64 * QSTR;
    unsigned* sVl = smem_u32 + 5 * 64 * QSTR;

    const int tid  = threadIdx.x;
    const int bh   = blockIdx.x / TILES;
    const int t_   = blockIdx.x % TILES;
    const int row0 = t_ * 64;
    const int nrows = min(64, NSEQ - row0);   // 64 or 32

    const size_t base = ((size_t)bh * NSEQ + row0) * 64;
    const float* qb = q + base;
    const float* kb = k + base;
    const float* vb = v + base;

    // ---- Single load phase: Q,K,V -> split bf16 smem (row-major, uint4 STS)
#pragma unroll
    for (int p = 0; p < 4; ++p) {
        int i  = tid + 128 * p;
        int r  = i >> 3;
        int c8 = (i & 7) << 3;
        float4 f0 = make_float4(0.f,0.f,0.f,0.f);
        float4 f1 = f0, g0 = f0, g1 = f0, v0 = f0, v1 = f0;
        if (r < nrows) {
            f0 = *(const float4*)(qb + r * 64 + c8);
            f1 = *(const float4*)(qb + r * 64 + c8 + 4);
            g0 = *(const float4*)(kb + r * 64 + c8);
            g1 = *(const float4*)(kb + r * 64 + c8 + 4);
            v0 = *(const float4*)(vb + r * 64 + c8);
            v1 = *(const float4*)(vb + r * 64 + c8 + 4);
        }
        unsigned h[4], l[4];
        split2(f0.x, f0.y, h[0], l[0]); split2(f0.z, f0.w, h[1], l[1]);
        split2(f1.x, f1.y, h[2], l[2]); split2(f1.z, f1.w, h[3], l[3]);
        *(uint4*)&sQh[r * QSTR + (c8 >> 1)] = make_uint4(h[0],h[1],h[2],h[3]);
        *(uint4*)&sQl[r * QSTR + (c8 >> 1)] = make_uint4(l[0],l[1],l[2],l[3]);
        split2(g0.x, g0.y, h[0], l[0]); split2(g0.z, g0.w, h[1], l[1]);
        split2(g1.x, g1.y, h[2], l[2]); split2(g1.z, g1.w, h[3], l[3]);
        *(uint4*)&sKh[r * QSTR + (c8 >> 1)] = make_uint4(h[0],h[1],h[2],h[3]);
        *(uint4*)&sKl[r * QSTR + (c8 >> 1)] = make_uint4(l[0],l[1],l[2],l[3]);
        split2(v0.x, v0.y, h[0], l[0]); split2(v0.z, v0.w, h[1], l[1]);
        split2(v1.x, v1.y, h[2], l[2]); split2(v1.z, v1.w, h[3], l[3]);
        *(uint4*)&sVh[r * QSTR + (c8 >> 1)] = make_uint4(h[0],h[1],h[2],h[3]);
        *(uint4*)&sVl[r * QSTR + (c8 >> 1)] = make_uint4(l[0],l[1],l[2],l[3]);
    }
    __syncthreads();   // the ONLY barrier

    const int lane = tid & 31;
    const int w    = tid >> 5;
    const int g    = lane >> 2;
    const int t    = lane & 3;
    const int i8   = lane >> 3;

    const unsigned sQh_b = (unsigned)__cvta_generic_to_shared(sQh);
    const unsigned sQl_b = (unsigned)__cvta_generic_to_shared(sQl);
    const unsigned sKh_b = (unsigned)__cvta_generic_to_shared(sKh);
    const unsigned sKl_b = (unsigned)__cvta_generic_to_shared(sKl);
    const unsigned sVh_b = (unsigned)__cvta_generic_to_shared(sVh);
    const unsigned sVl_b = (unsigned)__cvta_generic_to_shared(sVl);

    const int aRow = 16 * w + (i8 & 1) * 8 + (lane & 7);
    const unsigned aOff = aRow * 144 + (i8 >> 1) * 16;
    const unsigned bOff = ((i8 >> 1) * 8 + (lane & 7)) * 144 + (i8 & 1) * 16;
    const unsigned cOff = ((i8 & 1) * 8 + (lane & 7)) * 144 + (i8 >> 1) * 16;

    // ---- GEMM1: S = Q K^T  (hh + hl + lh)
    float acc[8][4];
#pragma unroll
    for (int ch = 0; ch < 8; ++ch)
#pragma unroll
        for (int j = 0; j < 4; ++j) acc[ch][j] = 0.f;

#pragma unroll
    for (int kk = 0; kk < 4; ++kk) {
        unsigned aH[4], aL[4];
        ldsm_x4(aH, sQh_b + aOff + kk * 32);
        ldsm_x4(aL, sQl_b + aOff + kk * 32);
#pragma unroll
        for (int chp = 0; chp < 4; ++chp) {
            unsigned bH[4], bL[4];
            ldsm_x4(bH, sKh_b + bOff + chp * 2304 + kk * 32);
            ldsm_x4(bL, sKl_b + bOff + chp * 2304 + kk * 32);
            mma16816(acc[2*chp],   aH, &bH[0]);
            mma16816(acc[2*chp],   aH, &bL[0]);
            mma16816(acc[2*chp],   aL, &bH[0]);
            mma16816(acc[2*chp+1], aH, &bH[2]);
            mma16816(acc[2*chp+1], aH, &bL[2]);
            mma16816(acc[2*chp+1], aL, &bH[2]);
        }
    }

    // ---- softmax (unnormalized; normalize at epilogue)
    float mx0 = -1e30f, mx1 = -1e30f;
#pragma unroll
    for (int ch = 0; ch < 8; ++ch) {
#pragma unroll
        for (int j = 0; j < 4; ++j) {
            int col = 8 * ch + 2 * t + (j & 1);
            acc[ch][j] = (col < nrows) ? acc[ch][j] * 0.125f : -1e30f;
        }
        mx0 = fmaxf(mx0, fmaxf(acc[ch][0], acc[ch][1]));
        mx1 = fmaxf(mx1, fmaxf(acc[ch][2], acc[ch][3]));
    }
    mx0 = fmaxf(mx0, __shfl_xor_sync(0xffffffffu, mx0, 1));
    mx0 = fmaxf(mx0, __shfl_xor_sync(0xffffffffu, mx0, 2));
    mx1 = fmaxf(mx1, __shfl_xor_sync(0xffffffffu, mx1, 1));
    mx1 = fmaxf(mx1, __shfl_xor_sync(0xffffffffu, mx1, 2));

    float sum0 = 0.f, sum1 = 0.f;
#pragma unroll
    for (int ch = 0; ch < 8; ++ch) {
        acc[ch][0] = __expf(acc[ch][0] - mx0);
        acc[ch][1] = __expf(acc[ch][1] - mx0);
        acc[ch][2] = __expf(acc[ch][2] - mx1);
        acc[ch][3] = __expf(acc[ch][3] - mx1);
        sum0 += acc[ch][0] + acc[ch][1];
        sum1 += acc[ch][2] + acc[ch][3];
    }
    sum0 += __shfl_xor_sync(0xffffffffu, sum0, 1);
    sum0 += __shfl_xor_sync(0xffffffffu, sum0, 2);
    sum1 += __shfl_xor_sync(0xffffffffu, sum1, 1);
    sum1 += __shfl_xor_sync(0xffffffffu, sum1, 2);

    // ---- eager P fragments (GEMM1 C-layout == GEMM2 A-layout)
    unsigned pH[4][4], pL[4][4];
#pragma unroll
    for (int kk = 0; kk < 4; ++kk) {
        split2(acc[2*kk][0],   acc[2*kk][1],   pH[kk][0], pL[kk][0]);
        split2(acc[2*kk][2],   acc[2*kk][3],   pH[kk][1], pL[kk][1]);
        split2(acc[2*kk+1][0], acc[2*kk+1][1], pH[kk][2], pL[kk][2]);
        split2(acc[2*kk+1][2], acc[2*kk+1][3], pH[kk][3], pL[kk][3]);
    }

    // ---- GEMM2: O = E V  (no barrier needed; V has dedicated buffers)
#pragma unroll
    for (int ch = 0; ch < 8; ++ch)
#pragma unroll
        for (int j = 0; j < 4; ++j) acc[ch][j] = 0.f;

#pragma unroll
    for (int kk = 0; kk < 4; ++kk) {
#pragma unroll
        for (int chp = 0; chp < 4; ++chp) {
            unsigned vH[4], vL[4];
            ldsm_x4_t(vH, sVh_b + cOff + kk * 2304 + chp * 32);
            ldsm_x4_t(vL, sVl_b + cOff + kk * 2304 + chp * 32);
            mma16816(acc[2*chp],   pH[kk], &vH[0]);
            mma16816(acc[2*chp],   pH[kk], &vL[0]);
            mma16816(acc[2*chp],   pL[kk], &vH[0]);
            mma16816(acc[2*chp+1], pH[kk], &vH[2]);
            mma16816(acc[2*chp+1], pH[kk], &vL[2]);
            mma16816(acc[2*chp+1], pL[kk], &vH[2]);
        }
    }

    // ---- epilogue: normalize and write
    const float inv0 = __frcp_rn(sum0);
    const float inv1 = __frcp_rn(sum1);
    float* ob = out + base;
    const int r0 = 16 * w + g;
    const int r1 = r0 + 8;
#pragma unroll
    for (int ch = 0; ch < 8; ++ch) {
        int col = 8 * ch + 2 * t;
        if (r0 < nrows)
            *(float2*)(ob + r0 * 64 + col) =
                make_float2(acc[ch][0] * inv0, acc[ch][1] * inv0);
        if (r1 < nrows)
            *(float2*)(ob + r1 * 64 + col) =
                make_float2(acc[ch][2] * inv1, acc[ch][3] * inv1);
    }
}

extern "C" void kernel_launch(void* const* d_in, const int* in_sizes, int n_in,
                              void* d_out, int out_size) {
    const float* q = (const float*)d_in[0];
    const float* k = (const float*)d_in[1];
    const float* v = (const float*)d_in[2];
    float* out = (float*)d_out;

    const int bh = in_sizes[0] / (NSEQ * 64);                      // 64
    const int smem_bytes = 6 * 64 * QSTR * (int)sizeof(unsigned);  // 55296

    cudaFuncSetAttribute(bd_attn_kernel,
                         cudaFuncAttributeMaxDynamicSharedMemorySize, smem_bytes);
    bd_attn_kernel<<<bh * TILES, 128, smem_bytes>>>(q, k, v, out);
}

// round 8
// speedup vs baseline: 1.1658x; 1.1658x over previous
#include <cuda_runtime.h>
#include <cuda_bf16.h>

// BlockDiagAttention: B=4,H=16,N=4128,D=64. fp32 in/out.
// R8 = R5 structure (best: 57.8us) + truncation split (PRMT hi, exact residual),
// deferred softmax normalization, batched V-phase loads. 5 CTAs/SM.
#define NSEQ  4128
#define TILES 65
#define QSTR  36   // u32 per smem row (144 B)

__device__ __forceinline__ void mma16816(float c[4], const unsigned a[4],
                                         const unsigned b[2]) {
    asm volatile(
        "mma.sync.aligned.m16n8k16.row.col.f32.bf16.bf16.f32 "
        "{%0,%1,%2,%3}, {%4,%5,%6,%7}, {%8,%9}, {%0,%1,%2,%3};"
        : "+f"(c[0]), "+f"(c[1]), "+f"(c[2]), "+f"(c[3])
        : "r"(a[0]), "r"(a[1]), "r"(a[2]), "r"(a[3]), "r"(b[0]), "r"(b[1]));
}

__device__ __forceinline__ void ldsm_x4(unsigned r[4], unsigned addr) {
    asm volatile("ldmatrix.sync.aligned.m8n8.x4.shared.b16 {%0,%1,%2,%3}, [%4];"
                 : "=r"(r[0]), "=r"(r[1]), "=r"(r[2]), "=r"(r[3]) : "r"(addr));
}

__device__ __forceinline__ void ldsm_x4_t(unsigned r[4], unsigned addr) {
    asm volatile("ldmatrix.sync.aligned.m8n8.x4.trans.shared.b16 {%0,%1,%2,%3}, [%4];"
                 : "=r"(r[0]), "=r"(r[1]), "=r"(r[2]), "=r"(r[3]) : "r"(addr));
}

// Truncation split: hi = upper 16 bits (exact bf16), lo = bf16(x - hi).
// hi-pair packed with a single PRMT; no f2f up-converts on the chain.
__device__ __forceinline__ void split2(float x0, float x1, unsigned& h, unsigned& l) {
    unsigned u0 = __float_as_uint(x0), u1 = __float_as_uint(x1);
    unsigned hh;
    asm("prmt.b32 %0, %1, %2, 0x7632;" : "=r"(hh) : "r"(u0), "r"(u1));
    float r0 = x0 - __uint_as_float(u0 & 0xFFFF0000u);
    float r1 = x1 - __uint_as_float(u1 & 0xFFFF0000u);
    __nv_bfloat162 ll = __floats2bfloat162_rn(r0, r1);
    h = hh;
    l = *(unsigned*)&ll;
}

extern __shared__ unsigned smem_u32[];

__global__ __launch_bounds__(128, 5)
void bd_attn_kernel(const float* __restrict__ q, const float* __restrict__ k,
                    const float* __restrict__ v, float* __restrict__ out)
{
    unsigned* sQh = smem_u32;              // later: V hi (row-major)
    unsigned* sQl = smem_u32 + 64 * QSTR;  // later: V lo
    unsigned* sKh = smem_u32 + 2 * 64 * QSTR;
    unsigned* sKl = smem_u32 + 3 * 64 * QSTR;

    const int tid  = threadIdx.x;
    const int bh   = blockIdx.x / TILES;
    const int t_   = blockIdx.x % TILES;
    const int row0 = t_ * 64;
    const int nrows = min(64, NSEQ - row0);   // 64 or 32

    const size_t base = ((size_t)bh * NSEQ + row0) * 64;
    const float* qb = q + base;
    const float* kb = k + base;
    const float* vb = v + base;

    // ---- L2 prefetch of V (consumed after GEMM1)
    {
        const char* vp = (const char*)vb;
        int lines = (nrows * 64 * 4) >> 7;
        for (int l = tid; l < lines; l += 128)
            asm volatile("prefetch.global.L2 [%0];" :: "l"(vp + (size_t)l * 128));
    }

    // ---- Load Q,K -> smem split bf16 (row-major, uint4 stores)
#pragma unroll
    for (int p = 0; p < 4; ++p) {
        int i  = tid + 128 * p;
        int r  = i >> 3;
        int c8 = (i & 7) << 3;
        float4 f0 = make_float4(0.f,0.f,0.f,0.f), f1 = f0, g0 = f0, g1 = f0;
        if (r < nrows) {
            f0 = *(const float4*)(qb + r * 64 + c8);
            f1 = *(const float4*)(qb + r * 64 + c8 + 4);
            g0 = *(const float4*)(kb + r * 64 + c8);
            g1 = *(const float4*)(kb + r * 64 + c8 + 4);
        }
        unsigned h[4], l[4];
        split2(f0.x, f0.y, h[0], l[0]); split2(f0.z, f0.w, h[1], l[1]);
        split2(f1.x, f1.y, h[2], l[2]); split2(f1.z, f1.w, h[3], l[3]);
        *(uint4*)&sQh[r * QSTR + (c8 >> 1)] = make_uint4(h[0],h[1],h[2],h[3]);
        *(uint4*)&sQl[r * QSTR + (c8 >> 1)] = make_uint4(l[0],l[1],l[2],l[3]);
        split2(g0.x, g0.y, h[0], l[0]); split2(g0.z, g0.w, h[1], l[1]);
        split2(g1.x, g1.y, h[2], l[2]); split2(g1.z, g1.w, h[3], l[3]);
        *(uint4*)&sKh[r * QSTR + (c8 >> 1)] = make_uint4(h[0],h[1],h[2],h[3]);
        *(uint4*)&sKl[r * QSTR + (c8 >> 1)] = make_uint4(l[0],l[1],l[2],l[3]);
    }
    __syncthreads();

    const int lane = tid & 31;
    const int w    = tid >> 5;
    const int g    = lane >> 2;
    const int t    = lane & 3;
    const int i8   = lane >> 3;

    const unsigned sQh_b = (unsigned)__cvta_generic_to_shared(sQh);
    const unsigned sQl_b = (unsigned)__cvta_generic_to_shared(sQl);
    const unsigned sKh_b = (unsigned)__cvta_generic_to_shared(sKh);
    const unsigned sKl_b = (unsigned)__cvta_generic_to_shared(sKl);

    const int aRow = 16 * w + (i8 & 1) * 8 + (lane & 7);
    const unsigned aOff = aRow * 144 + (i8 >> 1) * 16;
    const unsigned bOff = ((i8 >> 1) * 8 + (lane & 7)) * 144 + (i8 & 1) * 16;
    const unsigned cOff = ((i8 & 1) * 8 + (lane & 7)) * 144 + (i8 >> 1) * 16;

    // ---- GEMM1: S = Q K^T  (hh + hl + lh)
    float acc[8][4];
#pragma unroll
    for (int ch = 0; ch < 8; ++ch)
#pragma unroll
        for (int j = 0; j < 4; ++j) acc[ch][j] = 0.f;

#pragma unroll
    for (int kk = 0; kk < 4; ++kk) {
        unsigned aH[4], aL[4];
        ldsm_x4(aH, sQh_b + aOff + kk * 32);
        ldsm_x4(aL, sQl_b + aOff + kk * 32);
#pragma unroll
        for (int chp = 0; chp < 4; ++chp) {
            unsigned bH[4], bL[4];
            ldsm_x4(bH, sKh_b + bOff + chp * 2304 + kk * 32);
            ldsm_x4(bL, sKl_b + bOff + chp * 2304 + kk * 32);
            mma16816(acc[2*chp],   aH, &bH[0]);
            mma16816(acc[2*chp],   aH, &bL[0]);
            mma16816(acc[2*chp],   aL, &bH[0]);
            mma16816(acc[2*chp+1], aH, &bH[2]);
            mma16816(acc[2*chp+1], aH, &bL[2]);
            mma16816(acc[2*chp+1], aL, &bH[2]);
        }
    }

    // ---- softmax (unnormalized; normalize at epilogue)
    float mx0 = -1e30f, mx1 = -1e30f;
#pragma unroll
    for (int ch = 0; ch < 8; ++ch) {
#pragma unroll
        for (int j = 0; j < 4; ++j) {
            int col = 8 * ch + 2 * t + (j & 1);
            acc[ch][j] = (col < nrows) ? acc[ch][j] * 0.125f : -1e30f;
        }
        mx0 = fmaxf(mx0, fmaxf(acc[ch][0], acc[ch][1]));
        mx1 = fmaxf(mx1, fmaxf(acc[ch][2], acc[ch][3]));
    }
    mx0 = fmaxf(mx0, __shfl_xor_sync(0xffffffffu, mx0, 1));
    mx0 = fmaxf(mx0, __shfl_xor_sync(0xffffffffu, mx0, 2));
    mx1 = fmaxf(mx1, __shfl_xor_sync(0xffffffffu, mx1, 1));
    mx1 = fmaxf(mx1, __shfl_xor_sync(0xffffffffu, mx1, 2));

    float sum0 = 0.f, sum1 = 0.f;
#pragma unroll
    for (int ch = 0; ch < 8; ++ch) {
        acc[ch][0] = __expf(acc[ch][0] - mx0);
        acc[ch][1] = __expf(acc[ch][1] - mx0);
        acc[ch][2] = __expf(acc[ch][2] - mx1);
        acc[ch][3] = __expf(acc[ch][3] - mx1);
        sum0 += acc[ch][0] + acc[ch][1];
        sum1 += acc[ch][2] + acc[ch][3];
    }
    sum0 += __shfl_xor_sync(0xffffffffu, sum0, 1);
    sum0 += __shfl_xor_sync(0xffffffffu, sum0, 2);
    sum1 += __shfl_xor_sync(0xffffffffu, sum1, 1);
    sum1 += __shfl_xor_sync(0xffffffffu, sum1, 2);

    // ---- eager E fragments (unnormalized; E <= 1)
    unsigned pH[4][4], pL[4][4];
#pragma unroll
    for (int kk = 0; kk < 4; ++kk) {
        split2(acc[2*kk][0],   acc[2*kk][1],   pH[kk][0], pL[kk][0]);
        split2(acc[2*kk][2],   acc[2*kk][3],   pH[kk][1], pL[kk][1]);
        split2(acc[2*kk+1][0], acc[2*kk+1][1], pH[kk][2], pL[kk][2]);
        split2(acc[2*kk+1][2], acc[2*kk+1][3], pH[kk][3], pL[kk][3]);
    }

    __syncthreads();   // GEMM1 smem reads done; sQh/sQl become V hi/lo

    // ---- Load V -> smem split bf16, ROW-MAJOR (2-iter batched LDG)
#pragma unroll
    for (int p = 0; p < 2; ++p) {
        int i0 = tid + 256 * p;
        int i1 = i0 + 128;
        int r0v = i0 >> 3, c80 = (i0 & 7) << 3;
        int r1v = i1 >> 3, c81 = (i1 & 7) << 3;
        float4 a0 = make_float4(0.f,0.f,0.f,0.f), a1 = a0, b0 = a0, b1 = a0;
        if (r0v < nrows) {
            a0 = *(const float4*)(vb + r0v * 64 + c80);
            a1 = *(const float4*)(vb + r0v * 64 + c80 + 4);
        }
        if (r1v < nrows) {
            b0 = *(const float4*)(vb + r1v * 64 + c81);
            b1 = *(const float4*)(vb + r1v * 64 + c81 + 4);
        }
        unsigned h[4], l[4];
        split2(a0.x, a0.y, h[0], l[0]); split2(a0.z, a0.w, h[1], l[1]);
        split2(a1.x, a1.y, h[2], l[2]); split2(a1.z, a1.w, h[3], l[3]);
        *(uint4*)&sQh[r0v * QSTR + (c80 >> 1)] = make_uint4(h[0],h[1],h[2],h[3]);
        *(uint4*)&sQl[r0v * QSTR + (c80 >> 1)] = make_uint4(l[0],l[1],l[2],l[3]);
        split2(b0.x, b0.y, h[0], l[0]); split2(b0.z, b0.w, h[1], l[1]);
        split2(b1.x, b1.y, h[2], l[2]); split2(b1.z, b1.w, h[3], l[3]);
        *(uint4*)&sQh[r1v * QSTR + (c81 >> 1)] = make_uint4(h[0],h[1],h[2],h[3]);
        *(uint4*)&sQl[r1v * QSTR + (c81 >> 1)] = make_uint4(l[0],l[1],l[2],l[3]);
    }
    __syncthreads();

    // ---- GEMM2: O = E V
#pragma unroll
    for (int ch = 0; ch < 8; ++ch)
#pragma unroll
        for (int j = 0; j < 4; ++j) acc[ch][j] = 0.f;

#pragma unroll
    for (int kk = 0; kk < 4; ++kk) {
#pragma unroll
        for (int chp = 0; chp < 4; ++chp) {
            unsigned vH[4], vL[4];
            ldsm_x4_t(vH, sQh_b + cOff + kk * 2304 + chp * 32);
            ldsm_x4_t(vL, sQl_b + cOff + kk * 2304 + chp * 32);
            mma16816(acc[2*chp],   pH[kk], &vH[0]);
            mma16816(acc[2*chp],   pH[kk], &vL[0]);
            mma16816(acc[2*chp],   pL[kk], &vH[0]);
            mma16816(acc[2*chp+1], pH[kk], &vH[2]);
            mma16816(acc[2*chp+1], pH[kk], &vL[2]);
            mma16816(acc[2*chp+1], pL[kk], &vH[2]);
        }
    }

    // ---- epilogue: normalize and write
    const float inv0 = __frcp_rn(sum0);
    const float inv1 = __frcp_rn(sum1);
    float* ob = out + base;
    const int r0 = 16 * w + g;
    const int r1 = r0 + 8;
#pragma unroll
    for (int ch = 0; ch < 8; ++ch) {
        int col = 8 * ch + 2 * t;
        if (r0 < nrows)
            *(float2*)(ob + r0 * 64 + col) =
                make_float2(acc[ch][0] * inv0, acc[ch][1] * inv0);
        if (r1 < nrows)
            *(float2*)(ob + r1 * 64 + col) =
                make_float2(acc[ch][2] * inv1, acc[ch][3] * inv1);
    }
}

extern "C" void kernel_launch(void* const* d_in, const int* in_sizes, int n_in,
                              void* d_out, int out_size) {
    const float* q = (const float*)d_in[0];
    const float* k = (const float*)d_in[1];
    const float* v = (const float*)d_in[2];
    float* out = (float*)d_out;

    const int bh = in_sizes[0] / (NSEQ * 64);                      // 64
    const int smem_bytes = 4 * 64 * QSTR * (int)sizeof(unsigned);  // 36864

    cudaFuncSetAttribute(bd_attn_kernel,
                         cudaFuncAttributeMaxDynamicSharedMemorySize, smem_bytes);
    bd_attn_kernel<<<bh * TILES, 128, smem_bytes>>>(q, k, v, out);
}

// round 9
// speedup vs baseline: 1.1781x; 1.0105x over previous
#include <cuda_runtime.h>
#include <cuda_bf16.h>

// BlockDiagAttention: B=4,H=16,N=4128,D=64. fp32 in/out.
// R9 = R8 (trunc split, deferred norm, 5 CTAs/SM) + software-pipelined GEMM
// mainloops: double-buffered B/V ldmatrix fragments, ping-pong A fragments.
#define NSEQ  4128
#define TILES 65
#define QSTR  36   // u32 per smem row (144 B)

__device__ __forceinline__ void mma16816(float c[4], const unsigned a[4],
                                         const unsigned b[2]) {
    asm volatile(
        "mma.sync.aligned.m16n8k16.row.col.f32.bf16.bf16.f32 "
        "{%0,%1,%2,%3}, {%4,%5,%6,%7}, {%8,%9}, {%0,%1,%2,%3};"
        : "+f"(c[0]), "+f"(c[1]), "+f"(c[2]), "+f"(c[3])
        : "r"(a[0]), "r"(a[1]), "r"(a[2]), "r"(a[3]), "r"(b[0]), "r"(b[1]));
}

__device__ __forceinline__ void ldsm_x4(unsigned r[4], unsigned addr) {
    asm volatile("ldmatrix.sync.aligned.m8n8.x4.shared.b16 {%0,%1,%2,%3}, [%4];"
                 : "=r"(r[0]), "=r"(r[1]), "=r"(r[2]), "=r"(r[3]) : "r"(addr));
}

__device__ __forceinline__ void ldsm_x4_t(unsigned r[4], unsigned addr) {
    asm volatile("ldmatrix.sync.aligned.m8n8.x4.trans.shared.b16 {%0,%1,%2,%3}, [%4];"
                 : "=r"(r[0]), "=r"(r[1]), "=r"(r[2]), "=r"(r[3]) : "r"(addr));
}

// Truncation split: hi = upper 16 bits (exact bf16), lo = bf16(x - hi).
__device__ __forceinline__ void split2(float x0, float x1, unsigned& h, unsigned& l) {
    unsigned u0 = __float_as_uint(x0), u1 = __float_as_uint(x1);
    unsigned hh;
    asm("prmt.b32 %0, %1, %2, 0x7632;" : "=r"(hh) : "r"(u0), "r"(u1));
    float r0 = x0 - __uint_as_float(u0 & 0xFFFF0000u);
    float r1 = x1 - __uint_as_float(u1 & 0xFFFF0000u);
    __nv_bfloat162 ll = __floats2bfloat162_rn(r0, r1);
    h = hh;
    l = *(unsigned*)&ll;
}

extern __shared__ unsigned smem_u32[];

__global__ __launch_bounds__(128, 5)
void bd_attn_kernel(const float* __restrict__ q, const float* __restrict__ k,
                    const float* __restrict__ v, float* __restrict__ out)
{
    unsigned* sQh = smem_u32;              // later: V hi (row-major)
    unsigned* sQl = smem_u32 + 64 * QSTR;  // later: V lo
    unsigned* sKh = smem_u32 + 2 * 64 * QSTR;
    unsigned* sKl = smem_u32 + 3 * 64 * QSTR;

    const int tid  = threadIdx.x;
    const int bh   = blockIdx.x / TILES;
    const int t_   = blockIdx.x % TILES;
    const int row0 = t_ * 64;
    const int nrows = min(64, NSEQ - row0);   // 64 or 32

    const size_t base = ((size_t)bh * NSEQ + row0) * 64;
    const float* qb = q + base;
    const float* kb = k + base;
    const float* vb = v + base;

    // ---- L2 prefetch of V (consumed after GEMM1)
    {
        const char* vp = (const char*)vb;
        int lines = (nrows * 64 * 4) >> 7;
        for (int l = tid; l < lines; l += 128)
            asm volatile("prefetch.global.L2 [%0];" :: "l"(vp + (size_t)l * 128));
    }

    // ---- Load Q,K -> smem split bf16 (row-major, uint4 stores)
#pragma unroll
    for (int p = 0; p < 4; ++p) {
        int i  = tid + 128 * p;
        int r  = i >> 3;
        int c8 = (i & 7) << 3;
        float4 f0 = make_float4(0.f,0.f,0.f,0.f), f1 = f0, g0 = f0, g1 = f0;
        if (r < nrows) {
            f0 = *(const float4*)(qb + r * 64 + c8);
            f1 = *(const float4*)(qb + r * 64 + c8 + 4);
            g0 = *(const float4*)(kb + r * 64 + c8);
            g1 = *(const float4*)(kb + r * 64 + c8 + 4);
        }
        unsigned h[4], l[4];
        split2(f0.x, f0.y, h[0], l[0]); split2(f0.z, f0.w, h[1], l[1]);
        split2(f1.x, f1.y, h[2], l[2]); split2(f1.z, f1.w, h[3], l[3]);
        *(uint4*)&sQh[r * QSTR + (c8 >> 1)] = make_uint4(h[0],h[1],h[2],h[3]);
        *(uint4*)&sQl[r * QSTR + (c8 >> 1)] = make_uint4(l[0],l[1],l[2],l[3]);
        split2(g0.x, g0.y, h[0], l[0]); split2(g0.z, g0.w, h[1], l[1]);
        split2(g1.x, g1.y, h[2], l[2]); split2(g1.z, g1.w, h[3], l[3]);
        *(uint4*)&sKh[r * QSTR + (c8 >> 1)] = make_uint4(h[0],h[1],h[2],h[3]);
        *(uint4*)&sKl[r * QSTR + (c8 >> 1)] = make_uint4(l[0],l[1],l[2],l[3]);
    }
    __syncthreads();

    const int lane = tid & 31;
    const int w    = tid >> 5;
    const int g    = lane >> 2;
    const int t    = lane & 3;
    const int i8   = lane >> 3;

    const unsigned sQh_b = (unsigned)__cvta_generic_to_shared(sQh);
    const unsigned sQl_b = (unsigned)__cvta_generic_to_shared(sQl);
    const unsigned sKh_b = (unsigned)__cvta_generic_to_shared(sKh);
    const unsigned sKl_b = (unsigned)__cvta_generic_to_shared(sKl);

    const int aRow = 16 * w + (i8 & 1) * 8 + (lane & 7);
    const unsigned aOff = aRow * 144 + (i8 >> 1) * 16;
    const unsigned bOff = ((i8 >> 1) * 8 + (lane & 7)) * 144 + (i8 & 1) * 16;
    const unsigned cOff = ((i8 & 1) * 8 + (lane & 7)) * 144 + (i8 >> 1) * 16;

    // ---- GEMM1: S = Q K^T  (hh + hl + lh), software-pipelined
    float acc[8][4];
#pragma unroll
    for (int ch = 0; ch < 8; ++ch)
#pragma unroll
        for (int j = 0; j < 4; ++j) acc[ch][j] = 0.f;

    {
        unsigned aH[2][4], aL[2][4], bH[2][4], bL[2][4];
        ldsm_x4(aH[0], sQh_b + aOff);
        ldsm_x4(aL[0], sQl_b + aOff);
        ldsm_x4(bH[0], sKh_b + bOff);
        ldsm_x4(bL[0], sKl_b + bOff);
#pragma unroll
        for (int it = 0; it < 16; ++it) {
            const int kk  = it >> 2;
            const int chp = it & 3;
            const int cb  = it & 1;
            if (it < 15) {
                const int it2  = it + 1;
                const int kk2  = it2 >> 2;
                const int chp2 = it2 & 3;
                ldsm_x4(bH[it2 & 1], sKh_b + bOff + chp2 * 2304 + kk2 * 32);
                ldsm_x4(bL[it2 & 1], sKl_b + bOff + chp2 * 2304 + kk2 * 32);
                if (chp == 3) {
                    ldsm_x4(aH[kk2 & 1], sQh_b + aOff + kk2 * 32);
                    ldsm_x4(aL[kk2 & 1], sQl_b + aOff + kk2 * 32);
                }
            }
            const int ab = kk & 1;
            mma16816(acc[2*chp],   aH[ab], &bH[cb][0]);
            mma16816(acc[2*chp],   aH[ab], &bL[cb][0]);
            mma16816(acc[2*chp],   aL[ab], &bH[cb][0]);
            mma16816(acc[2*chp+1], aH[ab], &bH[cb][2]);
            mma16816(acc[2*chp+1], aH[ab], &bL[cb][2]);
            mma16816(acc[2*chp+1], aL[ab], &bH[cb][2]);
        }
    }

    // ---- softmax (unnormalized; normalize at epilogue)
    float mx0 = -1e30f, mx1 = -1e30f;
#pragma unroll
    for (int ch = 0; ch < 8; ++ch) {
#pragma unroll
        for (int j = 0; j < 4; ++j) {
            int col = 8 * ch + 2 * t + (j & 1);
            acc[ch][j] = (col < nrows) ? acc[ch][j] * 0.125f : -1e30f;
        }
        mx0 = fmaxf(mx0, fmaxf(acc[ch][0], acc[ch][1]));
        mx1 = fmaxf(mx1, fmaxf(acc[ch][2], acc[ch][3]));
    }
    mx0 = fmaxf(mx0, __shfl_xor_sync(0xffffffffu, mx0, 1));
    mx0 = fmaxf(mx0, __shfl_xor_sync(0xffffffffu, mx0, 2));
    mx1 = fmaxf(mx1, __shfl_xor_sync(0xffffffffu, mx1, 1));
    mx1 = fmaxf(mx1, __shfl_xor_sync(0xffffffffu, mx1, 2));

    float sum0 = 0.f, sum1 = 0.f;
#pragma unroll
    for (int ch = 0; ch < 8; ++ch) {
        acc[ch][0] = __expf(acc[ch][0] - mx0);
        acc[ch][1] = __expf(acc[ch][1] - mx0);
        acc[ch][2] = __expf(acc[ch][2] - mx1);
        acc[ch][3] = __expf(acc[ch][3] - mx1);
        sum0 += acc[ch][0] + acc[ch][1];
        sum1 += acc[ch][2] + acc[ch][3];
    }
    sum0 += __shfl_xor_sync(0xffffffffu, sum0, 1);
    sum0 += __shfl_xor_sync(0xffffffffu, sum0, 2);
    sum1 += __shfl_xor_sync(0xffffffffu, sum1, 1);
    sum1 += __shfl_xor_sync(0xffffffffu, sum1, 2);

    // ---- eager E fragments (unnormalized; E <= 1)
    unsigned pH[4][4], pL[4][4];
#pragma unroll
    for (int kk = 0; kk < 4; ++kk) {
        split2(acc[2*kk][0],   acc[2*kk][1],   pH[kk][0], pL[kk][0]);
        split2(acc[2*kk][2],   acc[2*kk][3],   pH[kk][1], pL[kk][1]);
        split2(acc[2*kk+1][0], acc[2*kk+1][1], pH[kk][2], pL[kk][2]);
        split2(acc[2*kk+1][2], acc[2*kk+1][3], pH[kk][3], pL[kk][3]);
    }

    __syncthreads();   // GEMM1 smem reads done; sQh/sQl become V hi/lo

    // ---- Load V -> smem split bf16, ROW-MAJOR: all LDGs issued first
    {
        float4 va[4][2];
#pragma unroll
        for (int p = 0; p < 4; ++p) {
            int i  = tid + 128 * p;
            int r  = i >> 3;
            int c8 = (i & 7) << 3;
            va[p][0] = make_float4(0.f,0.f,0.f,0.f);
            va[p][1] = va[p][0];
            if (r < nrows) {
                va[p][0] = *(const float4*)(vb + r * 64 + c8);
                va[p][1] = *(const float4*)(vb + r * 64 + c8 + 4);
            }
        }
#pragma unroll
        for (int p = 0; p < 4; ++p) {
            int i  = tid + 128 * p;
            int r  = i >> 3;
            int c8 = (i & 7) << 3;
            unsigned h[4], l[4];
            split2(va[p][0].x, va[p][0].y, h[0], l[0]);
            split2(va[p][0].z, va[p][0].w, h[1], l[1]);
            split2(va[p][1].x, va[p][1].y, h[2], l[2]);
            split2(va[p][1].z, va[p][1].w, h[3], l[3]);
            *(uint4*)&sQh[r * QSTR + (c8 >> 1)] = make_uint4(h[0],h[1],h[2],h[3]);
            *(uint4*)&sQl[r * QSTR + (c8 >> 1)] = make_uint4(l[0],l[1],l[2],l[3]);
        }
    }
    __syncthreads();

    // ---- GEMM2: O = E V, software-pipelined (V double-buffered)
#pragma unroll
    for (int ch = 0; ch < 8; ++ch)
#pragma unroll
        for (int j = 0; j < 4; ++j) acc[ch][j] = 0.f;

    {
        unsigned vH[2][4], vL[2][4];
        ldsm_x4_t(vH[0], sQh_b + cOff);
        ldsm_x4_t(vL[0], sQl_b + cOff);
#pragma unroll
        for (int it = 0; it < 16; ++it) {
            const int kk  = it >> 2;
            const int chp = it & 3;
            const int cb  = it & 1;
            if (it < 15) {
                const int it2  = it + 1;
                const int kk2  = it2 >> 2;
                const int chp2 = it2 & 3;
                ldsm_x4_t(vH[it2 & 1], sQh_b + cOff + kk2 * 2304 + chp2 * 32);
                ldsm_x4_t(vL[it2 & 1], sQl_b + cOff + kk2 * 2304 + chp2 * 32);
            }
            mma16816(acc[2*chp],   pH[kk], &vH[cb][0]);
            mma16816(acc[2*chp],   pH[kk], &vL[cb][0]);
            mma16816(acc[2*chp],   pL[kk], &vH[cb][0]);
            mma16816(acc[2*chp+1], pH[kk], &vH[cb][2]);
            mma16816(acc[2*chp+1], pH[kk], &vL[cb][2]);
            mma16816(acc[2*chp+1], pL[kk], &vH[cb][2]);
        }
    }

    // ---- epilogue: normalize and write
    const float inv0 = __frcp_rn(sum0);
    const float inv1 = __frcp_rn(sum1);
    float* ob = out + base;
    const int r0 = 16 * w + g;
    const int r1 = r0 + 8;
#pragma unroll
    for (int ch = 0; ch < 8; ++ch) {
        int col = 8 * ch + 2 * t;
        if (r0 < nrows)
            *(float2*)(ob + r0 * 64 + col) =
                make_float2(acc[ch][0] * inv0, acc[ch][1] * inv0);
        if (r1 < nrows)
            *(float2*)(ob + r1 * 64 + col) =
                make_float2(acc[ch][2] * inv1, acc[ch][3] * inv1);
    }
}

extern "C" void kernel_launch(void* const* d_in, const int* in_sizes, int n_in,
                              void* d_out, int out_size) {
    const float* q = (const float*)d_in[0];
    const float* k = (const float*)d_in[1];
    const float* v = (const float*)d_in[2];
    float* out = (float*)d_out;

    const int bh = in_sizes[0] / (NSEQ * 64);                      // 64
    const int smem_bytes = 4 * 64 * QSTR * (int)sizeof(unsigned);  // 36864

    cudaFuncSetAttribute(bd_attn_kernel,
                         cudaFuncAttributeMaxDynamicSharedMemorySize, smem_bytes);
    bd_attn_kernel<<<bh * TILES, 128, smem_bytes>>>(q, k, v, out);
}

// round 10
// speedup vs baseline: 1.2633x; 1.0724x over previous
#include <cuda_runtime.h>
#include <cuda_bf16.h>
#include <cuda_fp16.h>

// BlockDiagAttention: B=4,H=16,N=4128,D=64. fp32 in/out.
// R10 = R9 base; GEMM1 bf16 3-product (unchanged); GEMM2 in fp16 with
// compensated P (fp16 hi+lo) and SINGLE fp16 V -> V-lo buffer/STS/LDSM gone,
// GEMM2 MMAs 6->4 per iter. 5 CTAs/SM.
#define NSEQ  4128
#define TILES 65
#define QSTR  36   // u32 per smem row (144 B)

__device__ __forceinline__ void mma16816(float c[4], const unsigned a[4],
                                         const unsigned b[2]) {
    asm volatile(
        "mma.sync.aligned.m16n8k16.row.col.f32.bf16.bf16.f32 "
        "{%0,%1,%2,%3}, {%4,%5,%6,%7}, {%8,%9}, {%0,%1,%2,%3};"
        : "+f"(c[0]), "+f"(c[1]), "+f"(c[2]), "+f"(c[3])
        : "r"(a[0]), "r"(a[1]), "r"(a[2]), "r"(a[3]), "r"(b[0]), "r"(b[1]));
}

__device__ __forceinline__ void mma16816h(float c[4], const unsigned a[4],
                                          const unsigned b[2]) {
    asm volatile(
        "mma.sync.aligned.m16n8k16.row.col.f32.f16.f16.f32 "
        "{%0,%1,%2,%3}, {%4,%5,%6,%7}, {%8,%9}, {%0,%1,%2,%3};"
        : "+f"(c[0]), "+f"(c[1]), "+f"(c[2]), "+f"(c[3])
        : "r"(a[0]), "r"(a[1]), "r"(a[2]), "r"(a[3]), "r"(b[0]), "r"(b[1]));
}

__device__ __forceinline__ void ldsm_x4(unsigned r[4], unsigned addr) {
    asm volatile("ldmatrix.sync.aligned.m8n8.x4.shared.b16 {%0,%1,%2,%3}, [%4];"
                 : "=r"(r[0]), "=r"(r[1]), "=r"(r[2]), "=r"(r[3]) : "r"(addr));
}

__device__ __forceinline__ void ldsm_x4_t(unsigned r[4], unsigned addr) {
    asm volatile("ldmatrix.sync.aligned.m8n8.x4.trans.shared.b16 {%0,%1,%2,%3}, [%4];"
                 : "=r"(r[0]), "=r"(r[1]), "=r"(r[2]), "=r"(r[3]) : "r"(addr));
}

// bf16 truncation split: hi = upper 16 bits, lo = bf16(x - hi).
__device__ __forceinline__ void split2(float x0, float x1, unsigned& h, unsigned& l) {
    unsigned u0 = __float_as_uint(x0), u1 = __float_as_uint(x1);
    unsigned hh;
    asm("prmt.b32 %0, %1, %2, 0x7632;" : "=r"(hh) : "r"(u0), "r"(u1));
    float r0 = x0 - __uint_as_float(u0 & 0xFFFF0000u);
    float r1 = x1 - __uint_as_float(u1 & 0xFFFF0000u);
    __nv_bfloat162 ll = __floats2bfloat162_rn(r0, r1);
    h = hh;
    l = *(unsigned*)&ll;
}

// fp16 split: hi = f16(x), lo = f16(x - hi).  (x in [0,1] here)
__device__ __forceinline__ void split2h(float x0, float x1, unsigned& h, unsigned& l) {
    __half2 hh = __floats2half2_rn(x0, x1);
    float r0 = x0 - __half2float(__low2half(hh));
    float r1 = x1 - __half2float(__high2half(hh));
    __half2 ll = __floats2half2_rn(r0, r1);
    h = *(unsigned*)&hh;
    l = *(unsigned*)&ll;
}

extern __shared__ unsigned smem_u32[];

__global__ __launch_bounds__(128, 5)
void bd_attn_kernel(const float* __restrict__ q, const float* __restrict__ k,
                    const float* __restrict__ v, float* __restrict__ out)
{
    unsigned* sQh = smem_u32;              // later: V fp16 (row-major)
    unsigned* sQl = smem_u32 + 64 * QSTR;
    unsigned* sKh = smem_u32 + 2 * 64 * QSTR;
    unsigned* sKl = smem_u32 + 3 * 64 * QSTR;

    const int tid  = threadIdx.x;
    const int bh   = blockIdx.x / TILES;
    const int t_   = blockIdx.x % TILES;
    const int row0 = t_ * 64;
    const int nrows = min(64, NSEQ - row0);   // 64 or 32

    const size_t base = ((size_t)bh * NSEQ + row0) * 64;
    const float* qb = q + base;
    const float* kb = k + base;
    const float* vb = v + base;

    // ---- L2 prefetch of V (consumed after GEMM1)
    {
        const char* vp = (const char*)vb;
        int lines = (nrows * 64 * 4) >> 7;
        for (int l = tid; l < lines; l += 128)
            asm volatile("prefetch.global.L2 [%0];" :: "l"(vp + (size_t)l * 128));
    }

    // ---- Load Q,K -> smem split bf16 (row-major, uint4 stores)
#pragma unroll
    for (int p = 0; p < 4; ++p) {
        int i  = tid + 128 * p;
        int r  = i >> 3;
        int c8 = (i & 7) << 3;
        float4 f0 = make_float4(0.f,0.f,0.f,0.f), f1 = f0, g0 = f0, g1 = f0;
        if (r < nrows) {
            f0 = *(const float4*)(qb + r * 64 + c8);
            f1 = *(const float4*)(qb + r * 64 + c8 + 4);
            g0 = *(const float4*)(kb + r * 64 + c8);
            g1 = *(const float4*)(kb + r * 64 + c8 + 4);
        }
        unsigned h[4], l[4];
        split2(f0.x, f0.y, h[0], l[0]); split2(f0.z, f0.w, h[1], l[1]);
        split2(f1.x, f1.y, h[2], l[2]); split2(f1.z, f1.w, h[3], l[3]);
        *(uint4*)&sQh[r * QSTR + (c8 >> 1)] = make_uint4(h[0],h[1],h[2],h[3]);
        *(uint4*)&sQl[r * QSTR + (c8 >> 1)] = make_uint4(l[0],l[1],l[2],l[3]);
        split2(g0.x, g0.y, h[0], l[0]); split2(g0.z, g0.w, h[1], l[1]);
        split2(g1.x, g1.y, h[2], l[2]); split2(g1.z, g1.w, h[3], l[3]);
        *(uint4*)&sKh[r * QSTR + (c8 >> 1)] = make_uint4(h[0],h[1],h[2],h[3]);
        *(uint4*)&sKl[r * QSTR + (c8 >> 1)] = make_uint4(l[0],l[1],l[2],l[3]);
    }
    __syncthreads();

    const int lane = tid & 31;
    const int w    = tid >> 5;
    const int g    = lane >> 2;
    const int t    = lane & 3;
    const int i8   = lane >> 3;

    const unsigned sQh_b = (unsigned)__cvta_generic_to_shared(sQh);
    const unsigned sQl_b = (unsigned)__cvta_generic_to_shared(sQl);
    const unsigned sKh_b = (unsigned)__cvta_generic_to_shared(sKh);
    const unsigned sKl_b = (unsigned)__cvta_generic_to_shared(sKl);

    const int aRow = 16 * w + (i8 & 1) * 8 + (lane & 7);
    const unsigned aOff = aRow * 144 + (i8 >> 1) * 16;
    const unsigned bOff = ((i8 >> 1) * 8 + (lane & 7)) * 144 + (i8 & 1) * 16;
    const unsigned cOff = ((i8 & 1) * 8 + (lane & 7)) * 144 + (i8 >> 1) * 16;

    // ---- GEMM1: S = Q K^T  (hh + hl + lh), software-pipelined
    float acc[8][4];
#pragma unroll
    for (int ch = 0; ch < 8; ++ch)
#pragma unroll
        for (int j = 0; j < 4; ++j) acc[ch][j] = 0.f;

    {
        unsigned aH[2][4], aL[2][4], bH[2][4], bL[2][4];
        ldsm_x4(aH[0], sQh_b + aOff);
        ldsm_x4(aL[0], sQl_b + aOff);
        ldsm_x4(bH[0], sKh_b + bOff);
        ldsm_x4(bL[0], sKl_b + bOff);
#pragma unroll
        for (int it = 0; it < 16; ++it) {
            const int kk  = it >> 2;
            const int chp = it & 3;
            const int cb  = it & 1;
            if (it < 15) {
                const int it2  = it + 1;
                const int kk2  = it2 >> 2;
                const int chp2 = it2 & 3;
                ldsm_x4(bH[it2 & 1], sKh_b + bOff + chp2 * 2304 + kk2 * 32);
                ldsm_x4(bL[it2 & 1], sKl_b + bOff + chp2 * 2304 + kk2 * 32);
                if (chp == 3) {
                    ldsm_x4(aH[kk2 & 1], sQh_b + aOff + kk2 * 32);
                    ldsm_x4(aL[kk2 & 1], sQl_b + aOff + kk2 * 32);
                }
            }
            const int ab = kk & 1;
            mma16816(acc[2*chp],   aH[ab], &bH[cb][0]);
            mma16816(acc[2*chp],   aH[ab], &bL[cb][0]);
            mma16816(acc[2*chp],   aL[ab], &bH[cb][0]);
            mma16816(acc[2*chp+1], aH[ab], &bH[cb][2]);
            mma16816(acc[2*chp+1], aH[ab], &bL[cb][2]);
            mma16816(acc[2*chp+1], aL[ab], &bH[cb][2]);
        }
    }

    // ---- softmax (unnormalized; normalize at epilogue)
    float mx0 = -1e30f, mx1 = -1e30f;
#pragma unroll
    for (int ch = 0; ch < 8; ++ch) {
#pragma unroll
        for (int j = 0; j < 4; ++j) {
            int col = 8 * ch + 2 * t + (j & 1);
            acc[ch][j] = (col < nrows) ? acc[ch][j] * 0.125f : -1e30f;
        }
        mx0 = fmaxf(mx0, fmaxf(acc[ch][0], acc[ch][1]));
        mx1 = fmaxf(mx1, fmaxf(acc[ch][2], acc[ch][3]));
    }
    mx0 = fmaxf(mx0, __shfl_xor_sync(0xffffffffu, mx0, 1));
    mx0 = fmaxf(mx0, __shfl_xor_sync(0xffffffffu, mx0, 2));
    mx1 = fmaxf(mx1, __shfl_xor_sync(0xffffffffu, mx1, 1));
    mx1 = fmaxf(mx1, __shfl_xor_sync(0xffffffffu, mx1, 2));

    float sum0 = 0.f, sum1 = 0.f;
#pragma unroll
    for (int ch = 0; ch < 8; ++ch) {
        acc[ch][0] = __expf(acc[ch][0] - mx0);
        acc[ch][1] = __expf(acc[ch][1] - mx0);
        acc[ch][2] = __expf(acc[ch][2] - mx1);
        acc[ch][3] = __expf(acc[ch][3] - mx1);
        sum0 += acc[ch][0] + acc[ch][1];
        sum1 += acc[ch][2] + acc[ch][3];
    }
    sum0 += __shfl_xor_sync(0xffffffffu, sum0, 1);
    sum0 += __shfl_xor_sync(0xffffffffu, sum0, 2);
    sum1 += __shfl_xor_sync(0xffffffffu, sum1, 1);
    sum1 += __shfl_xor_sync(0xffffffffu, sum1, 2);

    // ---- eager E fragments: fp16 hi + lo (compensated; E <= 1)
    unsigned pH[4][4], pL[4][4];
#pragma unroll
    for (int kk = 0; kk < 4; ++kk) {
        split2h(acc[2*kk][0],   acc[2*kk][1],   pH[kk][0], pL[kk][0]);
        split2h(acc[2*kk][2],   acc[2*kk][3],   pH[kk][1], pL[kk][1]);
        split2h(acc[2*kk+1][0], acc[2*kk+1][1], pH[kk][2], pL[kk][2]);
        split2h(acc[2*kk+1][2], acc[2*kk+1][3], pH[kk][3], pL[kk][3]);
    }

    __syncthreads();   // GEMM1 smem reads done; sQh becomes V (fp16)

    // ---- Load V -> smem fp16, ROW-MAJOR (single buffer, all LDGs first)
    {
        float4 va[4][2];
#pragma unroll
        for (int p = 0; p < 4; ++p) {
            int i  = tid + 128 * p;
            int r  = i >> 3;
            int c8 = (i & 7) << 3;
            va[p][0] = make_float4(0.f,0.f,0.f,0.f);
            va[p][1] = va[p][0];
            if (r < nrows) {
                va[p][0] = *(const float4*)(vb + r * 64 + c8);
                va[p][1] = *(const float4*)(vb + r * 64 + c8 + 4);
            }
        }
#pragma unroll
        for (int p = 0; p < 4; ++p) {
            int i  = tid + 128 * p;
            int r  = i >> 3;
            int c8 = (i & 7) << 3;
            __half2 h0 = __floats2half2_rn(va[p][0].x, va[p][0].y);
            __half2 h1 = __floats2half2_rn(va[p][0].z, va[p][0].w);
            __half2 h2 = __floats2half2_rn(va[p][1].x, va[p][1].y);
            __half2 h3 = __floats2half2_rn(va[p][1].z, va[p][1].w);
            *(uint4*)&sQh[r * QSTR + (c8 >> 1)] =
                make_uint4(*(unsigned*)&h0, *(unsigned*)&h1,
                           *(unsigned*)&h2, *(unsigned*)&h3);
        }
    }
    __syncthreads();

    // ---- GEMM2: O = E V  (fp16: pH*V + pL*V), V double-buffered
#pragma unroll
    for (int ch = 0; ch < 8; ++ch)
#pragma unroll
        for (int j = 0; j < 4; ++j) acc[ch][j] = 0.f;

    {
        unsigned vH[2][4];
        ldsm_x4_t(vH[0], sQh_b + cOff);
#pragma unroll
        for (int it = 0; it < 16; ++it) {
            const int kk  = it >> 2;
            const int chp = it & 3;
            const int cb  = it & 1;
            if (it < 15) {
                const int it2  = it + 1;
                const int kk2  = it2 >> 2;
                const int chp2 = it2 & 3;
                ldsm_x4_t(vH[it2 & 1], sQh_b + cOff + kk2 * 2304 + chp2 * 32);
            }
            mma16816h(acc[2*chp],   pH[kk], &vH[cb][0]);
            mma16816h(acc[2*chp],   pL[kk], &vH[cb][0]);
            mma16816h(acc[2*chp+1], pH[kk], &vH[cb][2]);
            mma16816h(acc[2*chp+1], pL[kk], &vH[cb][2]);
        }
    }

    // ---- epilogue: normalize and write
    const float inv0 = __frcp_rn(sum0);
    const float inv1 = __frcp_rn(sum1);
    float* ob = out + base;
    const int r0 = 16 * w + g;
    const int r1 = r0 + 8;
#pragma unroll
    for (int ch = 0; ch < 8; ++ch) {
        int col = 8 * ch + 2 * t;
        if (r0 < nrows)
            *(float2*)(ob + r0 * 64 + col) =
                make_float2(acc[ch][0] * inv0, acc[ch][1] * inv0);
        if (r1 < nrows)
            *(float2*)(ob + r1 * 64 + col) =
                make_float2(acc[ch][2] * inv1, acc[ch][3] * inv1);
    }
}

extern "C" void kernel_launch(void* const* d_in, const int* in_sizes, int n_in,
                              void* d_out, int out_size) {
    const float* q = (const float*)d_in[0];
    const float* k = (const float*)d_in[1];
    const float* v = (const float*)d_in[2];
    float* out = (float*)d_out;

    const int bh = in_sizes[0] / (NSEQ * 64);                      // 64
    const int smem_bytes = 4 * 64 * QSTR * (int)sizeof(unsigned);  // 36864

    cudaFuncSetAttribute(bd_attn_kernel,
                         cudaFuncAttributeMaxDynamicSharedMemorySize, smem_bytes);
    bd_attn_kernel<<<bh * TILES, 128, smem_bytes>>>(q, k, v, out);
}

// round 11
// speedup vs baseline: 1.3733x; 1.0870x over previous
#include <cuda_runtime.h>
#include <cuda_bf16.h>
#include <cuda_fp16.h>

// BlockDiagAttention: B=4,H=16,N=4128,D=64. fp32 in/out.
// R11 = R10 + GEMM1 in fp16: Q compensated (hi+lo), K single fp16 ->
// K-lo buffer/STS/LDSM gone, GEMM1 MMAs 6->4 per iter. GEMM2 unchanged
// (P fp16 hi+lo, V single fp16). 5 CTAs/SM, smem 27.6KB.
#define NSEQ  4128
#define TILES 65
#define QSTR  36   // u32 per smem row (144 B)

__device__ __forceinline__ void mma16816h(float c[4], const unsigned a[4],
                                          const unsigned b[2]) {
    asm volatile(
        "mma.sync.aligned.m16n8k16.row.col.f32.f16.f16.f32 "
        "{%0,%1,%2,%3}, {%4,%5,%6,%7}, {%8,%9}, {%0,%1,%2,%3};"
        : "+f"(c[0]), "+f"(c[1]), "+f"(c[2]), "+f"(c[3])
        : "r"(a[0]), "r"(a[1]), "r"(a[2]), "r"(a[3]), "r"(b[0]), "r"(b[1]));
}

__device__ __forceinline__ void ldsm_x4(unsigned r[4], unsigned addr) {
    asm volatile("ldmatrix.sync.aligned.m8n8.x4.shared.b16 {%0,%1,%2,%3}, [%4];"
                 : "=r"(r[0]), "=r"(r[1]), "=r"(r[2]), "=r"(r[3]) : "r"(addr));
}

__device__ __forceinline__ void ldsm_x4_t(unsigned r[4], unsigned addr) {
    asm volatile("ldmatrix.sync.aligned.m8n8.x4.trans.shared.b16 {%0,%1,%2,%3}, [%4];"
                 : "=r"(r[0]), "=r"(r[1]), "=r"(r[2]), "=r"(r[3]) : "r"(addr));
}

// fp16 split: hi = f16(x), lo = f16(x - hi).
__device__ __forceinline__ void split2h(float x0, float x1, unsigned& h, unsigned& l) {
    __half2 hh = __floats2half2_rn(x0, x1);
    float r0 = x0 - __half2float(__low2half(hh));
    float r1 = x1 - __half2float(__high2half(hh));
    __half2 ll = __floats2half2_rn(r0, r1);
    h = *(unsigned*)&hh;
    l = *(unsigned*)&ll;
}

__device__ __forceinline__ unsigned pack2h(float x0, float x1) {
    __half2 hh = __floats2half2_rn(x0, x1);
    return *(unsigned*)&hh;
}

extern __shared__ unsigned smem_u32[];

__global__ __launch_bounds__(128, 5)
void bd_attn_kernel(const float* __restrict__ q, const float* __restrict__ k,
                    const float* __restrict__ v, float* __restrict__ out)
{
    unsigned* sQh = smem_u32;              // later: V fp16 (row-major)
    unsigned* sQl = smem_u32 + 64 * QSTR;
    unsigned* sK  = smem_u32 + 2 * 64 * QSTR;   // K fp16 (single)

    const int tid  = threadIdx.x;
    const int bh   = blockIdx.x / TILES;
    const int t_   = blockIdx.x % TILES;
    const int row0 = t_ * 64;
    const int nrows = min(64, NSEQ - row0);   // 64 or 32

    const size_t base = ((size_t)bh * NSEQ + row0) * 64;
    const float* qb = q + base;
    const float* kb = k + base;
    const float* vb = v + base;

    // ---- L2 prefetch of V (consumed after GEMM1)
    {
        const char* vp = (const char*)vb;
        int lines = (nrows * 64 * 4) >> 7;
        for (int l = tid; l < lines; l += 128)
            asm volatile("prefetch.global.L2 [%0];" :: "l"(vp + (size_t)l * 128));
    }

    // ---- Load Q (split fp16) and K (single fp16) -> smem
#pragma unroll
    for (int p = 0; p < 4; ++p) {
        int i  = tid + 128 * p;
        int r  = i >> 3;
        int c8 = (i & 7) << 3;
        float4 f0 = make_float4(0.f,0.f,0.f,0.f), f1 = f0, g0 = f0, g1 = f0;
        if (r < nrows) {
            f0 = *(const float4*)(qb + r * 64 + c8);
            f1 = *(const float4*)(qb + r * 64 + c8 + 4);
            g0 = *(const float4*)(kb + r * 64 + c8);
            g1 = *(const float4*)(kb + r * 64 + c8 + 4);
        }
        unsigned h[4], l[4];
        split2h(f0.x, f0.y, h[0], l[0]); split2h(f0.z, f0.w, h[1], l[1]);
        split2h(f1.x, f1.y, h[2], l[2]); split2h(f1.z, f1.w, h[3], l[3]);
        *(uint4*)&sQh[r * QSTR + (c8 >> 1)] = make_uint4(h[0],h[1],h[2],h[3]);
        *(uint4*)&sQl[r * QSTR + (c8 >> 1)] = make_uint4(l[0],l[1],l[2],l[3]);
        *(uint4*)&sK[r * QSTR + (c8 >> 1)] =
            make_uint4(pack2h(g0.x, g0.y), pack2h(g0.z, g0.w),
                       pack2h(g1.x, g1.y), pack2h(g1.z, g1.w));
    }
    __syncthreads();

    const int lane = tid & 31;
    const int w    = tid >> 5;
    const int g    = lane >> 2;
    const int t    = lane & 3;
    const int i8   = lane >> 3;

    const unsigned sQh_b = (unsigned)__cvta_generic_to_shared(sQh);
    const unsigned sQl_b = (unsigned)__cvta_generic_to_shared(sQl);
    const unsigned sK_b  = (unsigned)__cvta_generic_to_shared(sK);

    const int aRow = 16 * w + (i8 & 1) * 8 + (lane & 7);
    const unsigned aOff = aRow * 144 + (i8 >> 1) * 16;
    const unsigned bOff = ((i8 >> 1) * 8 + (lane & 7)) * 144 + (i8 & 1) * 16;
    const unsigned cOff = ((i8 & 1) * 8 + (lane & 7)) * 144 + (i8 >> 1) * 16;

    // ---- GEMM1: S = Q K^T  (fp16: QhK + QlK), software-pipelined
    float acc[8][4];
#pragma unroll
    for (int ch = 0; ch < 8; ++ch)
#pragma unroll
        for (int j = 0; j < 4; ++j) acc[ch][j] = 0.f;

    {
        unsigned aH[2][4], aL[2][4], bH[2][4];
        ldsm_x4(aH[0], sQh_b + aOff);
        ldsm_x4(aL[0], sQl_b + aOff);
        ldsm_x4(bH[0], sK_b + bOff);
#pragma unroll
        for (int it = 0; it < 16; ++it) {
            const int kk  = it >> 2;
            const int chp = it & 3;
            const int cb  = it & 1;
            if (it < 15) {
                const int it2  = it + 1;
                const int kk2  = it2 >> 2;
                const int chp2 = it2 & 3;
                ldsm_x4(bH[it2 & 1], sK_b + bOff + chp2 * 2304 + kk2 * 32);
                if (chp == 3) {
                    ldsm_x4(aH[kk2 & 1], sQh_b + aOff + kk2 * 32);
                    ldsm_x4(aL[kk2 & 1], sQl_b + aOff + kk2 * 32);
                }
            }
            const int ab = kk & 1;
            mma16816h(acc[2*chp],   aH[ab], &bH[cb][0]);
            mma16816h(acc[2*chp],   aL[ab], &bH[cb][0]);
            mma16816h(acc[2*chp+1], aH[ab], &bH[cb][2]);
            mma16816h(acc[2*chp+1], aL[ab], &bH[cb][2]);
        }
    }

    // ---- softmax (unnormalized; normalize at epilogue)
    float mx0 = -1e30f, mx1 = -1e30f;
#pragma unroll
    for (int ch = 0; ch < 8; ++ch) {
#pragma unroll
        for (int j = 0; j < 4; ++j) {
            int col = 8 * ch + 2 * t + (j & 1);
            acc[ch][j] = (col < nrows) ? acc[ch][j] * 0.125f : -1e30f;
        }
        mx0 = fmaxf(mx0, fmaxf(acc[ch][0], acc[ch][1]));
        mx1 = fmaxf(mx1, fmaxf(acc[ch][2], acc[ch][3]));
    }
    mx0 = fmaxf(mx0, __shfl_xor_sync(0xffffffffu, mx0, 1));
    mx0 = fmaxf(mx0, __shfl_xor_sync(0xffffffffu, mx0, 2));
    mx1 = fmaxf(mx1, __shfl_xor_sync(0xffffffffu, mx1, 1));
    mx1 = fmaxf(mx1, __shfl_xor_sync(0xffffffffu, mx1, 2));

    float sum0 = 0.f, sum1 = 0.f;
#pragma unroll
    for (int ch = 0; ch < 8; ++ch) {
        acc[ch][0] = __expf(acc[ch][0] - mx0);
        acc[ch][1] = __expf(acc[ch][1] - mx0);
        acc[ch][2] = __expf(acc[ch][2] - mx1);
        acc[ch][3] = __expf(acc[ch][3] - mx1);
        sum0 += acc[ch][0] + acc[ch][1];
        sum1 += acc[ch][2] + acc[ch][3];
    }
    sum0 += __shfl_xor_sync(0xffffffffu, sum0, 1);
    sum0 += __shfl_xor_sync(0xffffffffu, sum0, 2);
    sum1 += __shfl_xor_sync(0xffffffffu, sum1, 1);
    sum1 += __shfl_xor_sync(0xffffffffu, sum1, 2);

    // ---- eager E fragments: fp16 hi + lo (compensated; E <= 1)
    unsigned pH[4][4], pL[4][4];
#pragma unroll
    for (int kk = 0; kk < 4; ++kk) {
        split2h(acc[2*kk][0],   acc[2*kk][1],   pH[kk][0], pL[kk][0]);
        split2h(acc[2*kk][2],   acc[2*kk][3],   pH[kk][1], pL[kk][1]);
        split2h(acc[2*kk+1][0], acc[2*kk+1][1], pH[kk][2], pL[kk][2]);
        split2h(acc[2*kk+1][2], acc[2*kk+1][3], pH[kk][3], pL[kk][3]);
    }

    __syncthreads();   // GEMM1 smem reads done; sQh becomes V (fp16)

    // ---- Load V -> smem fp16, ROW-MAJOR (single buffer, all LDGs first)
    {
        float4 va[4][2];
#pragma unroll
        for (int p = 0; p < 4; ++p) {
            int i  = tid + 128 * p;
            int r  = i >> 3;
            int c8 = (i & 7) << 3;
            va[p][0] = make_float4(0.f,0.f,0.f,0.f);
            va[p][1] = va[p][0];
            if (r < nrows) {
                va[p][0] = *(const float4*)(vb + r * 64 + c8);
                va[p][1] = *(const float4*)(vb + r * 64 + c8 + 4);
            }
        }
#pragma unroll
        for (int p = 0; p < 4; ++p) {
            int i  = tid + 128 * p;
            int r  = i >> 3;
            int c8 = (i & 7) << 3;
            *(uint4*)&sQh[r * QSTR + (c8 >> 1)] =
                make_uint4(pack2h(va[p][0].x, va[p][0].y),
                           pack2h(va[p][0].z, va[p][0].w),
                           pack2h(va[p][1].x, va[p][1].y),
                           pack2h(va[p][1].z, va[p][1].w));
        }
    }
    __syncthreads();

    // ---- GEMM2: O = E V  (fp16: pH*V + pL*V), V double-buffered
#pragma unroll
    for (int ch = 0; ch < 8; ++ch)
#pragma unroll
        for (int j = 0; j < 4; ++j) acc[ch][j] = 0.f;

    {
        unsigned vH[2][4];
        ldsm_x4_t(vH[0], sQh_b + cOff);
#pragma unroll
        for (int it = 0; it < 16; ++it) {
            const int kk  = it >> 2;
            const int chp = it & 3;
            const int cb  = it & 1;
            if (it < 15) {
                const int it2  = it + 1;
                const int kk2  = it2 >> 2;
                const int chp2 = it2 & 3;
                ldsm_x4_t(vH[it2 & 1], sQh_b + cOff + kk2 * 2304 + chp2 * 32);
            }
            mma16816h(acc[2*chp],   pH[kk], &vH[cb][0]);
            mma16816h(acc[2*chp],   pL[kk], &vH[cb][0]);
            mma16816h(acc[2*chp+1], pH[kk], &vH[cb][2]);
            mma16816h(acc[2*chp+1], pL[kk], &vH[cb][2]);
        }
    }

    // ---- epilogue: normalize and write
    const float inv0 = __frcp_rn(sum0);
    const float inv1 = __frcp_rn(sum1);
    float* ob = out + base;
    const int r0 = 16 * w + g;
    const int r1 = r0 + 8;
#pragma unroll
    for (int ch = 0; ch < 8; ++ch) {
        int col = 8 * ch + 2 * t;
        if (r0 < nrows)
            *(float2*)(ob + r0 * 64 + col) =
                make_float2(acc[ch][0] * inv0, acc[ch][1] * inv0);
        if (r1 < nrows)
            *(float2*)(ob + r1 * 64 + col) =
                make_float2(acc[ch][2] * inv1, acc[ch][3] * inv1);
    }
}

extern "C" void kernel_launch(void* const* d_in, const int* in_sizes, int n_in,
                              void* d_out, int out_size) {
    const float* q = (const float*)d_in[0];
    const float* k = (const float*)d_in[1];
    const float* v = (const float*)d_in[2];
    float* out = (float*)d_out;

    const int bh = in_sizes[0] / (NSEQ * 64);                      // 64
    const int smem_bytes = 3 * 64 * QSTR * (int)sizeof(unsigned);  // 27648

    cudaFuncSetAttribute(bd_attn_kernel,
                         cudaFuncAttributeMaxDynamicSharedMemorySize, smem_bytes);
    bd_attn_kernel<<<bh * TILES, 128, smem_bytes>>>(q, k, v, out);
}

// round 12
// speedup vs baseline: 1.4324x; 1.0430x over previous
#include <cuda_runtime.h>
#include <cuda_bf16.h>
#include <cuda_fp16.h>

// BlockDiagAttention: B=4,H=16,N=4128,D=64. fp32 in/out.
// R12 = R11 with GEMM1 fully fp16 (Q single, K single -> 2 MMAs/iter -> 1 prod);
// P stays compensated fp16 hi+lo for GEMM2, V single fp16. 5 CTAs/SM, 18.4KB smem.
#define NSEQ  4128
#define TILES 65
#define QSTR  36   // u32 per smem row (144 B)

__device__ __forceinline__ void mma16816h(float c[4], const unsigned a[4],
                                          const unsigned b[2]) {
    asm volatile(
        "mma.sync.aligned.m16n8k16.row.col.f32.f16.f16.f32 "
        "{%0,%1,%2,%3}, {%4,%5,%6,%7}, {%8,%9}, {%0,%1,%2,%3};"
        : "+f"(c[0]), "+f"(c[1]), "+f"(c[2]), "+f"(c[3])
        : "r"(a[0]), "r"(a[1]), "r"(a[2]), "r"(a[3]), "r"(b[0]), "r"(b[1]));
}

__device__ __forceinline__ void ldsm_x4(unsigned r[4], unsigned addr) {
    asm volatile("ldmatrix.sync.aligned.m8n8.x4.shared.b16 {%0,%1,%2,%3}, [%4];"
                 : "=r"(r[0]), "=r"(r[1]), "=r"(r[2]), "=r"(r[3]) : "r"(addr));
}

__device__ __forceinline__ void ldsm_x4_t(unsigned r[4], unsigned addr) {
    asm volatile("ldmatrix.sync.aligned.m8n8.x4.trans.shared.b16 {%0,%1,%2,%3}, [%4];"
                 : "=r"(r[0]), "=r"(r[1]), "=r"(r[2]), "=r"(r[3]) : "r"(addr));
}

// fp16 split: hi = f16(x), lo = f16(x - hi).
__device__ __forceinline__ void split2h(float x0, float x1, unsigned& h, unsigned& l) {
    __half2 hh = __floats2half2_rn(x0, x1);
    float r0 = x0 - __half2float(__low2half(hh));
    float r1 = x1 - __half2float(__high2half(hh));
    __half2 ll = __floats2half2_rn(r0, r1);
    h = *(unsigned*)&hh;
    l = *(unsigned*)&ll;
}

__device__ __forceinline__ unsigned pack2h(float x0, float x1) {
    __half2 hh = __floats2half2_rn(x0, x1);
    return *(unsigned*)&hh;
}

extern __shared__ unsigned smem_u32[];

__global__ __launch_bounds__(128, 5)
void bd_attn_kernel(const float* __restrict__ q, const float* __restrict__ k,
                    const float* __restrict__ v, float* __restrict__ out)
{
    unsigned* sQ = smem_u32;               // Q fp16; later V fp16 (row-major)
    unsigned* sK = smem_u32 + 64 * QSTR;   // K fp16

    const int tid  = threadIdx.x;
    const int bh   = blockIdx.x / TILES;
    const int t_   = blockIdx.x % TILES;
    const int row0 = t_ * 64;
    const int nrows = min(64, NSEQ - row0);   // 64 or 32

    const size_t base = ((size_t)bh * NSEQ + row0) * 64;
    const float* qb = q + base;
    const float* kb = k + base;
    const float* vb = v + base;

    // ---- L2 prefetch of V (consumed after GEMM1)
    {
        const char* vp = (const char*)vb;
        int lines = (nrows * 64 * 4) >> 7;
        for (int l = tid; l < lines; l += 128)
            asm volatile("prefetch.global.L2 [%0];" :: "l"(vp + (size_t)l * 128));
    }

    // ---- Load Q,K -> smem fp16 (row-major, uint4 stores)
#pragma unroll
    for (int p = 0; p < 4; ++p) {
        int i  = tid + 128 * p;
        int r  = i >> 3;
        int c8 = (i & 7) << 3;
        float4 f0 = make_float4(0.f,0.f,0.f,0.f), f1 = f0, g0 = f0, g1 = f0;
        if (r < nrows) {
            f0 = *(const float4*)(qb + r * 64 + c8);
            f1 = *(const float4*)(qb + r * 64 + c8 + 4);
            g0 = *(const float4*)(kb + r * 64 + c8);
            g1 = *(const float4*)(kb + r * 64 + c8 + 4);
        }
        *(uint4*)&sQ[r * QSTR + (c8 >> 1)] =
            make_uint4(pack2h(f0.x, f0.y), pack2h(f0.z, f0.w),
                       pack2h(f1.x, f1.y), pack2h(f1.z, f1.w));
        *(uint4*)&sK[r * QSTR + (c8 >> 1)] =
            make_uint4(pack2h(g0.x, g0.y), pack2h(g0.z, g0.w),
                       pack2h(g1.x, g1.y), pack2h(g1.z, g1.w));
    }
    __syncthreads();

    const int lane = tid & 31;
    const int w    = tid >> 5;
    const int g    = lane >> 2;
    const int t    = lane & 3;
    const int i8   = lane >> 3;

    const unsigned sQ_b = (unsigned)__cvta_generic_to_shared(sQ);
    const unsigned sK_b = (unsigned)__cvta_generic_to_shared(sK);

    const int aRow = 16 * w + (i8 & 1) * 8 + (lane & 7);
    const unsigned aOff = aRow * 144 + (i8 >> 1) * 16;
    const unsigned bOff = ((i8 >> 1) * 8 + (lane & 7)) * 144 + (i8 & 1) * 16;
    const unsigned cOff = ((i8 & 1) * 8 + (lane & 7)) * 144 + (i8 >> 1) * 16;

    // ---- GEMM1: S = Q K^T  (pure fp16, fp32 accum), software-pipelined
    float acc[8][4];
#pragma unroll
    for (int ch = 0; ch < 8; ++ch)
#pragma unroll
        for (int j = 0; j < 4; ++j) acc[ch][j] = 0.f;

    {
        unsigned aH[2][4], bH[2][4];
        ldsm_x4(aH[0], sQ_b + aOff);
        ldsm_x4(bH[0], sK_b + bOff);
#pragma unroll
        for (int it = 0; it < 16; ++it) {
            const int kk  = it >> 2;
            const int chp = it & 3;
            const int cb  = it & 1;
            if (it < 15) {
                const int it2  = it + 1;
                const int kk2  = it2 >> 2;
                const int chp2 = it2 & 3;
                ldsm_x4(bH[it2 & 1], sK_b + bOff + chp2 * 2304 + kk2 * 32);
                if (chp == 3)
                    ldsm_x4(aH[kk2 & 1], sQ_b + aOff + kk2 * 32);
            }
            const int ab = kk & 1;
            mma16816h(acc[2*chp],   aH[ab], &bH[cb][0]);
            mma16816h(acc[2*chp+1], aH[ab], &bH[cb][2]);
        }
    }

    // ---- softmax (unnormalized; normalize at epilogue)
    float mx0 = -1e30f, mx1 = -1e30f;
#pragma unroll
    for (int ch = 0; ch < 8; ++ch) {
#pragma unroll
        for (int j = 0; j < 4; ++j) {
            int col = 8 * ch + 2 * t + (j & 1);
            acc[ch][j] = (col < nrows) ? acc[ch][j] * 0.125f : -1e30f;
        }
        mx0 = fmaxf(mx0, fmaxf(acc[ch][0], acc[ch][1]));
        mx1 = fmaxf(mx1, fmaxf(acc[ch][2], acc[ch][3]));
    }
    mx0 = fmaxf(mx0, __shfl_xor_sync(0xffffffffu, mx0, 1));
    mx0 = fmaxf(mx0, __shfl_xor_sync(0xffffffffu, mx0, 2));
    mx1 = fmaxf(mx1, __shfl_xor_sync(0xffffffffu, mx1, 1));
    mx1 = fmaxf(mx1, __shfl_xor_sync(0xffffffffu, mx1, 2));

    float sum0 = 0.f, sum1 = 0.f;
#pragma unroll
    for (int ch = 0; ch < 8; ++ch) {
        acc[ch][0] = __expf(acc[ch][0] - mx0);
        acc[ch][1] = __expf(acc[ch][1] - mx0);
        acc[ch][2] = __expf(acc[ch][2] - mx1);
        acc[ch][3] = __expf(acc[ch][3] - mx1);
        sum0 += acc[ch][0] + acc[ch][1];
        sum1 += acc[ch][2] + acc[ch][3];
    }
    sum0 += __shfl_xor_sync(0xffffffffu, sum0, 1);
    sum0 += __shfl_xor_sync(0xffffffffu, sum0, 2);
    sum1 += __shfl_xor_sync(0xffffffffu, sum1, 1);
    sum1 += __shfl_xor_sync(0xffffffffu, sum1, 2);

    // ---- eager E fragments: fp16 hi + lo (compensated; E <= 1)
    unsigned pH[4][4], pL[4][4];
#pragma unroll
    for (int kk = 0; kk < 4; ++kk) {
        split2h(acc[2*kk][0],   acc[2*kk][1],   pH[kk][0], pL[kk][0]);
        split2h(acc[2*kk][2],   acc[2*kk][3],   pH[kk][1], pL[kk][1]);
        split2h(acc[2*kk+1][0], acc[2*kk+1][1], pH[kk][2], pL[kk][2]);
        split2h(acc[2*kk+1][2], acc[2*kk+1][3], pH[kk][3], pL[kk][3]);
    }

    __syncthreads();   // GEMM1 smem reads done; sQ becomes V (fp16)

    // ---- Load V -> smem fp16, ROW-MAJOR (all LDGs first)
    {
        float4 va[4][2];
#pragma unroll
        for (int p = 0; p < 4; ++p) {
            int i  = tid + 128 * p;
            int r  = i >> 3;
            int c8 = (i & 7) << 3;
            va[p][0] = make_float4(0.f,0.f,0.f,0.f);
            va[p][1] = va[p][0];
            if (r < nrows) {
                va[p][0] = *(const float4*)(vb + r * 64 + c8);
                va[p][1] = *(const float4*)(vb + r * 64 + c8 + 4);
            }
        }
#pragma unroll
        for (int p = 0; p < 4; ++p) {
            int i  = tid + 128 * p;
            int r  = i >> 3;
            int c8 = (i & 7) << 3;
            *(uint4*)&sQ[r * QSTR + (c8 >> 1)] =
                make_uint4(pack2h(va[p][0].x, va[p][0].y),
                           pack2h(va[p][0].z, va[p][0].w),
                           pack2h(va[p][1].x, va[p][1].y),
                           pack2h(va[p][1].z, va[p][1].w));
        }
    }
    __syncthreads();

    // ---- GEMM2: O = E V  (fp16: pH*V + pL*V), V double-buffered
#pragma unroll
    for (int ch = 0; ch < 8; ++ch)
#pragma unroll
        for (int j = 0; j < 4; ++j) acc[ch][j] = 0.f;

    {
        unsigned vH[2][4];
        ldsm_x4_t(vH[0], sQ_b + cOff);
#pragma unroll
        for (int it = 0; it < 16; ++it) {
            const int kk  = it >> 2;
            const int chp = it & 3;
            const int cb  = it & 1;
            if (it < 15) {
                const int it2  = it + 1;
                const int kk2  = it2 >> 2;
                const int chp2 = it2 & 3;
                ldsm_x4_t(vH[it2 & 1], sQ_b + cOff + kk2 * 2304 + chp2 * 32);
            }
            mma16816h(acc[2*chp],   pH[kk], &vH[cb][0]);
            mma16816h(acc[2*chp],   pL[kk], &vH[cb][0]);
            mma16816h(acc[2*chp+1], pH[kk], &vH[cb][2]);
            mma16816h(acc[2*chp+1], pL[kk], &vH[cb][2]);
        }
    }

    // ---- epilogue: normalize and write
    const float inv0 = __frcp_rn(sum0);
    const float inv1 = __frcp_rn(sum1);
    float* ob = out + base;
    const int r0 = 16 * w + g;
    const int r1 = r0 + 8;
#pragma unroll
    for (int ch = 0; ch < 8; ++ch) {
        int col = 8 * ch + 2 * t;
        if (r0 < nrows)
            *(float2*)(ob + r0 * 64 + col) =
                make_float2(acc[ch][0] * inv0, acc[ch][1] * inv0);
        if (r1 < nrows)
            *(float2*)(ob + r1 * 64 + col) =
                make_float2(acc[ch][2] * inv1, acc[ch][3] * inv1);
    }
}

extern "C" void kernel_launch(void* const* d_in, const int* in_sizes, int n_in,
                              void* d_out, int out_size) {
    const float* q = (const float*)d_in[0];
    const float* k = (const float*)d_in[1];
    const float* v = (const float*)d_in[2];
    float* out = (float*)d_out;

    const int bh = in_sizes[0] / (NSEQ * 64);                      // 64
    const int smem_bytes = 2 * 64 * QSTR * (int)sizeof(unsigned);  // 18432

    cudaFuncSetAttribute(bd_attn_kernel,
                         cudaFuncAttributeMaxDynamicSharedMemorySize, smem_bytes);
    bd_attn_kernel<<<bh * TILES, 128, smem_bytes>>>(q, k, v, out);
}